// round 1
// baseline (speedup 1.0000x reference)
#include <cuda_runtime.h>
#include <math.h>

#define HDIM 2048
#define IDIM 2048
#define NEXP 16
#define TOPK 4
#define ALPHA 1.702f
#define LIMIT 7.0f
#define T_MAX 4096
#define BM 64
#define BN 64
#define BK 16
#define MAX_ROWS (T_MAX*TOPK + NEXP*BM)   /* 17408 (segments padded to BM) */
#define MAX_TILES (MAX_ROWS/BM)           /* 272 */

// ---------------- scratch (static device globals; no allocation) ------------
__device__ int   g_topk_idx[T_MAX*TOPK];
__device__ float g_topk_w[T_MAX*TOPK];
__device__ int   g_cnt[NEXP];
__device__ int   g_off[NEXP];
__device__ int   g_pair_tok[MAX_ROWS];
__device__ float g_pair_w[MAX_ROWS];
__device__ int   g_tile_expert[MAX_TILES];
__device__ float g_act[(size_t)MAX_ROWS * IDIM];   // ~142 MB

// ---------------- router: logits + top4 + softmax ---------------------------
__global__ void __launch_bounds__(128) router_kernel(
    const float* __restrict__ x, const float* __restrict__ rw,
    const float* __restrict__ rb, int T)
{
    int t = blockIdx.x;
    if (t >= T) return;
    int tid = threadIdx.x;
    int e = tid >> 3;          // 16 experts x 8 threads
    int s = tid & 7;

    const float4* xr = (const float4*)(x + (size_t)t * HDIM);
    const float4* wr = (const float4*)(rw + (size_t)e * HDIM);
    float acc = 0.f;
    for (int j = s; j < HDIM/4; j += 8) {
        float4 a = xr[j], b = wr[j];
        acc += a.x*b.x + a.y*b.y + a.z*b.z + a.w*b.w;
    }
    acc += __shfl_down_sync(0xffffffffu, acc, 4, 8);
    acc += __shfl_down_sync(0xffffffffu, acc, 2, 8);
    acc += __shfl_down_sync(0xffffffffu, acc, 1, 8);

    __shared__ float s_logit[NEXP];
    if (s == 0) s_logit[e] = acc + rb[e];
    __syncthreads();

    if (tid == 0) {
        float v[NEXP];
        #pragma unroll
        for (int i = 0; i < NEXP; i++) v[i] = s_logit[i];
        int   bi[TOPK];
        float bv[TOPK];
        unsigned used = 0;
        #pragma unroll
        for (int k = 0; k < TOPK; k++) {
            int best = -1; float bval = -INFINITY;
            #pragma unroll
            for (int i = 0; i < NEXP; i++) {
                if (!((used >> i) & 1u) && v[i] > bval) { bval = v[i]; best = i; }
            }
            used |= (1u << best);
            bi[k] = best; bv[k] = bval;
        }
        float m = bv[0];
        float w[TOPK], sum = 0.f;
        #pragma unroll
        for (int k = 0; k < TOPK; k++) { w[k] = expf(bv[k] - m); sum += w[k]; }
        float inv = 1.f / sum;
        #pragma unroll
        for (int k = 0; k < TOPK; k++) {
            g_topk_idx[t*TOPK + k] = bi[k];
            g_topk_w[t*TOPK + k]   = w[k] * inv;
        }
    }
}

// ---------------- per-expert counts ------------------------------------------
__global__ void __launch_bounds__(256) count_kernel(int T)
{
    int e = blockIdx.x, tid = threadIdx.x;
    int c = 0;
    for (int t = tid; t < T; t += 256) {
        #pragma unroll
        for (int k = 0; k < TOPK; k++)
            if (g_topk_idx[t*TOPK + k] == e) c++;
    }
    __shared__ int red[256];
    red[tid] = c; __syncthreads();
    for (int sft = 128; sft > 0; sft >>= 1) {
        if (tid < sft) red[tid] += red[tid + sft];
        __syncthreads();
    }
    if (tid == 0) g_cnt[e] = red[0];
}

// ---------------- init pair arrays / tile map --------------------------------
__global__ void init_kernel()
{
    int i = blockIdx.x * blockDim.x + threadIdx.x;
    if (i < MAX_ROWS) g_pair_tok[i] = -1;
    if (i < MAX_TILES) g_tile_expert[i] = -1;
}

// ---------------- offsets (BM-padded segments) + tile->expert map ------------
__global__ void offsets_kernel()
{
    int off = 0;
    for (int e = 0; e < NEXP; e++) {
        g_off[e] = off;
        int padded = ((g_cnt[e] + BM - 1) / BM) * BM;
        for (int t = off / BM; t < (off + padded) / BM; t++) g_tile_expert[t] = e;
        off += padded;
    }
}

// ---------------- stable compaction (token order preserved) ------------------
__global__ void __launch_bounds__(256) fill_kernel(int T)
{
    int e = blockIdx.x, tid = threadIdx.x;
    int lane = tid & 31, wid = tid >> 5;
    __shared__ int s_base, s_wcnt[8], s_wpre[8], s_total;
    if (tid == 0) s_base = g_off[e];
    __syncthreads();

    for (int t0 = 0; t0 < T; t0 += 256) {
        int t = t0 + tid;
        int kf = -1;
        if (t < T) {
            #pragma unroll
            for (int k = 0; k < TOPK; k++)
                if (g_topk_idx[t*TOPK + k] == e) { kf = k; break; }
        }
        int flag = (kf >= 0);
        unsigned b = __ballot_sync(0xffffffffu, flag);
        int pos = __popc(b & ((1u << lane) - 1u));
        if (lane == 0) s_wcnt[wid] = __popc(b);
        __syncthreads();
        if (tid == 0) {
            int a = 0;
            #pragma unroll
            for (int w = 0; w < 8; w++) { s_wpre[w] = a; a += s_wcnt[w]; }
            s_total = a;
        }
        __syncthreads();
        if (flag) {
            int p = s_base + s_wpre[wid] + pos;
            g_pair_tok[p] = t;
            g_pair_w[p]   = g_topk_w[t*TOPK + kf];
        }
        __syncthreads();
        if (tid == 0) s_base += s_total;
        __syncthreads();
    }
}

// ---------------- GEMM1: act = glu(x @ w1 + b1) ------------------------------
__global__ void __launch_bounds__(256) gemm1_kernel(
    const float* __restrict__ x, const float* __restrict__ w1,
    const float* __restrict__ b1)
{
    int by = blockIdx.y;
    int e = g_tile_expert[by];
    if (e < 0) return;
    int n0 = blockIdx.x * BN;
    int row0 = by * BM;
    int tid = threadIdx.x;
    int tx = tid & 15, ty = tid >> 4;

    __shared__ float As[BK][BM];
    __shared__ float Bg[BK][BN];
    __shared__ float Bu[BK][BN];
    __shared__ int   s_tok[BM];

    if (tid < BM) s_tok[tid] = g_pair_tok[row0 + tid];
    __syncthreads();

    const float* w1e = w1 + (size_t)e * HDIM * (2*IDIM);
    float accg[4][4] = {}, accu[4][4] = {};

    for (int k0 = 0; k0 < HDIM; k0 += BK) {
        #pragma unroll
        for (int i = 0; i < 4; i++) {
            int idx = tid + i*256;
            int m = idx >> 4, kk = idx & 15;
            int tok = s_tok[m];
            As[kk][m] = (tok >= 0) ? x[(size_t)tok*HDIM + k0 + kk] : 0.f;
        }
        #pragma unroll
        for (int i = 0; i < 4; i++) {
            int idx = tid + i*256;
            int kk = idx >> 6, n = idx & 63;
            const float* wrow = w1e + (size_t)(k0 + kk) * (2*IDIM);
            Bg[kk][n] = wrow[n0 + n];
            Bu[kk][n] = wrow[IDIM + n0 + n];
        }
        __syncthreads();
        #pragma unroll
        for (int kk = 0; kk < BK; kk++) {
            float4 a4 = *(const float4*)&As[kk][ty*4];
            float4 g4 = *(const float4*)&Bg[kk][tx*4];
            float4 u4 = *(const float4*)&Bu[kk][tx*4];
            float a[4] = {a4.x, a4.y, a4.z, a4.w};
            float g[4] = {g4.x, g4.y, g4.z, g4.w};
            float u[4] = {u4.x, u4.y, u4.z, u4.w};
            #pragma unroll
            for (int i = 0; i < 4; i++)
                #pragma unroll
                for (int j = 0; j < 4; j++) {
                    accg[i][j] += a[i] * g[j];
                    accu[i][j] += a[i] * u[j];
                }
        }
        __syncthreads();
    }

    const float* b1e = b1 + (size_t)e * (2*IDIM);
    #pragma unroll
    for (int i = 0; i < 4; i++) {
        int m = ty*4 + i;
        size_t rbase = (size_t)(row0 + m) * IDIM;
        #pragma unroll
        for (int j = 0; j < 4; j++) {
            int n = n0 + tx*4 + j;
            float gate = accg[i][j] + b1e[n];
            float up   = accu[i][j] + b1e[IDIM + n];
            gate = fminf(gate, LIMIT);
            up   = fminf(fmaxf(up, -LIMIT), LIMIT);
            float sig = 1.f / (1.f + expf(-ALPHA * gate));
            g_act[rbase + n] = (up + 1.f) * gate * sig;
        }
    }
}

// ---------------- GEMM2: out += w * (act @ w2 + b2) --------------------------
__global__ void __launch_bounds__(256) gemm2_kernel(
    const float* __restrict__ w2, const float* __restrict__ b2,
    float* __restrict__ out)
{
    int by = blockIdx.y;
    int e = g_tile_expert[by];
    if (e < 0) return;
    int n0 = blockIdx.x * BN;
    int row0 = by * BM;
    int tid = threadIdx.x;
    int tx = tid & 15, ty = tid >> 4;

    __shared__ float As[BK][BM];
    __shared__ float Bs[BK][BN];
    __shared__ int   s_tok[BM];
    __shared__ float s_w[BM];

    if (tid < BM) {
        s_tok[tid] = g_pair_tok[row0 + tid];
        s_w[tid]   = g_pair_w[row0 + tid];
    }
    __syncthreads();

    const float* w2e = w2 + (size_t)e * IDIM * HDIM;
    float acc[4][4] = {};

    for (int k0 = 0; k0 < IDIM; k0 += BK) {
        #pragma unroll
        for (int i = 0; i < 4; i++) {
            int idx = tid + i*256;
            int m = idx >> 4, kk = idx & 15;
            As[kk][m] = g_act[(size_t)(row0 + m) * IDIM + k0 + kk];
        }
        #pragma unroll
        for (int i = 0; i < 4; i++) {
            int idx = tid + i*256;
            int kk = idx >> 6, n = idx & 63;
            Bs[kk][n] = w2e[(size_t)(k0 + kk) * HDIM + n0 + n];
        }
        __syncthreads();
        #pragma unroll
        for (int kk = 0; kk < BK; kk++) {
            float4 a4 = *(const float4*)&As[kk][ty*4];
            float4 b4 = *(const float4*)&Bs[kk][tx*4];
            float a[4] = {a4.x, a4.y, a4.z, a4.w};
            float b[4] = {b4.x, b4.y, b4.z, b4.w};
            #pragma unroll
            for (int i = 0; i < 4; i++)
                #pragma unroll
                for (int j = 0; j < 4; j++)
                    acc[i][j] += a[i] * b[j];
        }
        __syncthreads();
    }

    const float* b2e = b2 + (size_t)e * HDIM;
    #pragma unroll
    for (int i = 0; i < 4; i++) {
        int m = ty*4 + i;
        int tok = s_tok[m];
        if (tok < 0) continue;
        float w = s_w[m];
        #pragma unroll
        for (int j = 0; j < 4; j++) {
            int n = n0 + tx*4 + j;
            float v = acc[i][j] + b2e[n];
            atomicAdd(&out[(size_t)tok * HDIM + n], w * v);
        }
    }
}

// ---------------- launch ------------------------------------------------------
extern "C" void kernel_launch(void* const* d_in, const int* in_sizes, int n_in,
                              void* d_out, int out_size)
{
    const float* x  = (const float*)d_in[0];
    const float* rw = (const float*)d_in[1];
    const float* rb = (const float*)d_in[2];
    const float* w1 = (const float*)d_in[3];
    const float* b1 = (const float*)d_in[4];
    const float* w2 = (const float*)d_in[5];
    const float* b2 = (const float*)d_in[6];
    float* out = (float*)d_out;

    int T = in_sizes[0] / HDIM;
    if (T > T_MAX) T = T_MAX;

    cudaMemsetAsync(out, 0, (size_t)T * HDIM * sizeof(float));

    router_kernel<<<T, 128>>>(x, rw, rb, T);
    count_kernel<<<NEXP, 256>>>(T);
    init_kernel<<<(MAX_ROWS + 255)/256, 256>>>();
    offsets_kernel<<<1, 1>>>();
    fill_kernel<<<NEXP, 256>>>(T);
    gemm1_kernel<<<dim3(IDIM/BN, MAX_TILES), 256>>>(x, w1, b1);
    gemm2_kernel<<<dim3(HDIM/BN, MAX_TILES), 256>>>(w2, b2, out);
}

// round 3
// speedup vs baseline: 10.2490x; 10.2490x over previous
#include <cuda_runtime.h>
#include <cuda_fp16.h>
#include <math.h>
#include <stdint.h>

#define HDIM 2048
#define IDIM 2048
#define NEXP 16
#define TOPK 4
#define ALPHA 1.702f
#define LIMIT 7.0f
#define T_MAX 4096
#define BM 128
#define BN 128
#define BK 64
#define KC (HDIM/BK)              /* 32 */
#define NSTAGE 3
#define MAX_ROWS (T_MAX*TOPK + NEXP*BM)   /* 18432 */
#define MAX_TILES (MAX_ROWS/BM)           /* 144 */

// smem layout gemm1: A 3x16KB @0, Bg 3x16KB @49152, Bu 3x16KB @98304
#define ST_A 16384
#define OFF_BG 49152
#define OFF_BU 98304
#define SMEM1 147456
// gemm2: A 3x16KB @0, B 3x16KB @49152
#define OFF_B2 49152
#define SMEM2 98304

// ------------------------- scratch (static device) ---------------------------
__device__ __half g_w1h[(size_t)NEXP*HDIM*2*IDIM];   // 268 MB
__device__ __half g_w2h[(size_t)NEXP*IDIM*HDIM];     // 134 MB
__device__ __half g_xh[(size_t)T_MAX*HDIM];          // 16 MB
__device__ __half g_acth[(size_t)MAX_ROWS*IDIM];     // 75 MB
__device__ int   g_topk_idx[T_MAX*TOPK];
__device__ float g_topk_w[T_MAX*TOPK];
__device__ int   g_cnt[NEXP];
__device__ int   g_off[NEXP];
__device__ int   g_pair_tok[MAX_ROWS];
__device__ float g_pair_w[MAX_ROWS];
__device__ int   g_tile_expert[MAX_TILES];

// ------------------------- asm helpers --------------------------------------
__device__ __forceinline__ uint32_t smem_u32(const void* p) {
    uint32_t a;
    asm("{ .reg .u64 t; cvta.to.shared.u64 t, %1; cvt.u32.u64 %0, t; }"
        : "=r"(a) : "l"(p));
    return a;
}
__device__ __forceinline__ uint32_t swzA(uint32_t off) {   // 128B rows
    return off ^ ((off >> 3) & 0x70);
}
__device__ __forceinline__ uint32_t swzB(uint32_t off) {   // 256B rows
    return off ^ (((off >> 8) & 7) << 4);
}
#define CP16(dst, src) \
    asm volatile("cp.async.cg.shared.global [%0], [%1], 16;\n" :: "r"(dst), "l"(src))
#define CP16Z(dst, src, sz) \
    asm volatile("cp.async.cg.shared.global [%0], [%1], 16, %2;\n" :: "r"(dst), "l"(src), "r"(sz))
#define CP_COMMIT() asm volatile("cp.async.commit_group;\n" ::: "memory")
#define CP_WAIT1() asm volatile("cp.async.wait_group 1;\n" ::: "memory")
#define CP_WAIT0() asm volatile("cp.async.wait_group 0;\n" ::: "memory")
#define LDSM4(r0,r1,r2,r3,a) \
    asm volatile("ldmatrix.sync.aligned.m8n8.x4.shared.b16 {%0,%1,%2,%3}, [%4];\n" \
        : "=r"(r0),"=r"(r1),"=r"(r2),"=r"(r3) : "r"(a))
#define LDSM4T(r0,r1,r2,r3,a) \
    asm volatile("ldmatrix.sync.aligned.m8n8.x4.trans.shared.b16 {%0,%1,%2,%3}, [%4];\n" \
        : "=r"(r0),"=r"(r1),"=r"(r2),"=r"(r3) : "r"(a))
#define MMA16816(d, a, b) \
    asm volatile("mma.sync.aligned.m16n8k16.row.col.f32.f16.f16.f32 " \
        "{%0,%1,%2,%3}, {%4,%5,%6,%7}, {%8,%9}, {%0,%1,%2,%3};\n" \
        : "+f"((d)[0]),"+f"((d)[1]),"+f"((d)[2]),"+f"((d)[3]) \
        : "r"((a)[0]),"r"((a)[1]),"r"((a)[2]),"r"((a)[3]), "r"((b)[0]),"r"((b)[1]))

__device__ __forceinline__ float actf(float g, float u) {
    g = fminf(g, LIMIT);
    u = fminf(fmaxf(u, -LIMIT), LIMIT);
    return (u + 1.f) * g / (1.f + expf(-ALPHA * g));
}

// ---------------- fp32 -> fp16 conversion ------------------------------------
__global__ void __launch_bounds__(256) cvt_kernel(const float4* __restrict__ src,
                                                  uint2* __restrict__ dst, int n)
{
    int i = blockIdx.x * blockDim.x + threadIdx.x;
    int stride = gridDim.x * blockDim.x;
    for (; i < n; i += stride) {
        float4 v = src[i];
        __half2 h0 = __floats2half2_rn(v.x, v.y);
        __half2 h1 = __floats2half2_rn(v.z, v.w);
        uint2 o;
        o.x = *reinterpret_cast<uint32_t*>(&h0);
        o.y = *reinterpret_cast<uint32_t*>(&h1);
        dst[i] = o;
    }
}

// ---------------- router: logits + top4 + softmax ---------------------------
__global__ void __launch_bounds__(128) router_kernel(
    const float* __restrict__ x, const float* __restrict__ rw,
    const float* __restrict__ rb, int T)
{
    int t = blockIdx.x;
    if (t >= T) return;
    int tid = threadIdx.x;
    int e = tid >> 3;
    int s = tid & 7;

    const float4* xr = (const float4*)(x + (size_t)t * HDIM);
    const float4* wr = (const float4*)(rw + (size_t)e * HDIM);
    float acc = 0.f;
    for (int j = s; j < HDIM/4; j += 8) {
        float4 a = xr[j], b = wr[j];
        acc += a.x*b.x + a.y*b.y + a.z*b.z + a.w*b.w;
    }
    acc += __shfl_down_sync(0xffffffffu, acc, 4, 8);
    acc += __shfl_down_sync(0xffffffffu, acc, 2, 8);
    acc += __shfl_down_sync(0xffffffffu, acc, 1, 8);

    __shared__ float s_logit[NEXP];
    if (s == 0) s_logit[e] = acc + rb[e];
    __syncthreads();

    if (tid == 0) {
        float v[NEXP];
        #pragma unroll
        for (int i = 0; i < NEXP; i++) v[i] = s_logit[i];
        int   bi[TOPK];
        float bv[TOPK];
        unsigned used = 0;
        #pragma unroll
        for (int k = 0; k < TOPK; k++) {
            int best = -1; float bval = -INFINITY;
            #pragma unroll
            for (int i = 0; i < NEXP; i++) {
                if (!((used >> i) & 1u) && v[i] > bval) { bval = v[i]; best = i; }
            }
            used |= (1u << best);
            bi[k] = best; bv[k] = bval;
        }
        float m = bv[0];
        float w[TOPK], sum = 0.f;
        #pragma unroll
        for (int k = 0; k < TOPK; k++) { w[k] = expf(bv[k] - m); sum += w[k]; }
        float inv = 1.f / sum;
        #pragma unroll
        for (int k = 0; k < TOPK; k++) {
            g_topk_idx[t*TOPK + k] = bi[k];
            g_topk_w[t*TOPK + k]   = w[k] * inv;
        }
    }
}

__global__ void __launch_bounds__(256) count_kernel(int T)
{
    int e = blockIdx.x, tid = threadIdx.x;
    int c = 0;
    for (int t = tid; t < T; t += 256) {
        #pragma unroll
        for (int k = 0; k < TOPK; k++)
            if (g_topk_idx[t*TOPK + k] == e) c++;
    }
    __shared__ int red[256];
    red[tid] = c; __syncthreads();
    for (int sft = 128; sft > 0; sft >>= 1) {
        if (tid < sft) red[tid] += red[tid + sft];
        __syncthreads();
    }
    if (tid == 0) g_cnt[e] = red[0];
}

__global__ void init_kernel()
{
    int i = blockIdx.x * blockDim.x + threadIdx.x;
    if (i < MAX_ROWS) g_pair_tok[i] = -1;
    if (i < MAX_TILES) g_tile_expert[i] = -1;
}

__global__ void offsets_kernel()
{
    int off = 0;
    for (int e = 0; e < NEXP; e++) {
        g_off[e] = off;
        int padded = ((g_cnt[e] + BM - 1) / BM) * BM;
        for (int t = off / BM; t < (off + padded) / BM; t++) g_tile_expert[t] = e;
        off += padded;
    }
}

__global__ void __launch_bounds__(256) fill_kernel(int T)
{
    int e = blockIdx.x, tid = threadIdx.x;
    int lane = tid & 31, wid = tid >> 5;
    __shared__ int s_base, s_wcnt[8], s_wpre[8], s_total;
    if (tid == 0) s_base = g_off[e];
    __syncthreads();

    for (int t0 = 0; t0 < T; t0 += 256) {
        int t = t0 + tid;
        int kf = -1;
        if (t < T) {
            #pragma unroll
            for (int k = 0; k < TOPK; k++)
                if (g_topk_idx[t*TOPK + k] == e) { kf = k; break; }
        }
        int flag = (kf >= 0);
        unsigned b = __ballot_sync(0xffffffffu, flag);
        int pos = __popc(b & ((1u << lane) - 1u));
        if (lane == 0) s_wcnt[wid] = __popc(b);
        __syncthreads();
        if (tid == 0) {
            int a = 0;
            #pragma unroll
            for (int w = 0; w < 8; w++) { s_wpre[w] = a; a += s_wcnt[w]; }
            s_total = a;
        }
        __syncthreads();
        if (flag) {
            int p = s_base + s_wpre[wid] + pos;
            g_pair_tok[p] = t;
            g_pair_w[p]   = g_topk_w[t*TOPK + kf];
        }
        __syncthreads();
        if (tid == 0) s_base += s_total;
        __syncthreads();
    }
}

// ---------------- GEMM1 (mma.sync fp16): acth = glu(x @ w1 + b1) -------------
__global__ void __launch_bounds__(256, 1) gemm1_kernel(const float* __restrict__ b1)
{
    int by = blockIdx.y;
    int e = g_tile_expert[by];
    if (e < 0) return;
    int n0 = blockIdx.x * BN;
    int row0 = by * BM;
    int tid = threadIdx.x, lane = tid & 31, wid = tid >> 5;
    int wm = wid & 1, wn = wid >> 1;

    extern __shared__ char smem[];
    uint32_t sb = smem_u32(smem);
    __shared__ int s_tok[BM];
    if (tid < BM) s_tok[tid] = g_pair_tok[row0 + tid];
    __syncthreads();

    const __half* w1e = g_w1h + (size_t)e * HDIM * (2*IDIM);

    auto issue = [&](int kc) {
        int slot = kc % NSTAGE;
        uint32_t abase = sb + slot * ST_A;
        uint32_t gbase = sb + OFF_BG + slot * ST_A;
        uint32_t ubase = sb + OFF_BU + slot * ST_A;
        int k0 = kc * BK;
        #pragma unroll
        for (int i = 0; i < 4; i++) {
            int id = tid + i * 256;
            int r = id >> 3, c = id & 7;
            int tok = s_tok[r];
            const __half* src = g_xh + (size_t)(tok < 0 ? 0 : tok) * HDIM + k0 + c*8;
            int sz = (tok >= 0) ? 16 : 0;
            CP16Z(abase + swzA((uint32_t)(r*128 + c*16)), src, sz);
        }
        #pragma unroll
        for (int i = 0; i < 4; i++) {
            int id = tid + i * 256;
            int r = id >> 4, c = id & 15;
            const __half* srcg = w1e + (size_t)(k0 + r) * (2*IDIM) + n0 + c*8;
            uint32_t off = swzB((uint32_t)(r*256 + c*16));
            CP16(gbase + off, srcg);
            CP16(ubase + off, srcg + IDIM);
        }
        CP_COMMIT();
    };

    float ag[4][4][4] = {}, au[4][4][4] = {};
    issue(0); issue(1);

    for (int kc = 0; kc < KC; kc++) {
        int slot = kc % NSTAGE;
        if (kc >= KC - 2) { CP_WAIT0(); } else { CP_WAIT1(); }
        __syncthreads();
        uint32_t abase = sb + slot * ST_A;
        uint32_t gbase = sb + OFF_BG + slot * ST_A;
        uint32_t ubase = sb + OFF_BU + slot * ST_A;
        #pragma unroll
        for (int k16 = 0; k16 < 4; k16++) {
            uint32_t a[4][4];
            #pragma unroll
            for (int mt = 0; mt < 4; mt++) {
                int mrow = wm*64 + mt*16 + (lane & 15);
                uint32_t addr = abase + swzA((uint32_t)(mrow*128 + (k16*2 + (lane>>4))*16));
                LDSM4(a[mt][0], a[mt][1], a[mt][2], a[mt][3], addr);
            }
            uint32_t bg[4][2], bu[4][2];
            #pragma unroll
            for (int h = 0; h < 2; h++) {
                int krow = k16*16 + (lane & 15);
                int nh = wn*32 + h*16 + (lane>>4)*8;
                uint32_t off = swzB((uint32_t)(krow*256 + nh*2));
                uint32_t r0,r1,r2,r3;
                LDSM4T(r0,r1,r2,r3, gbase + off);
                bg[h*2][0]=r0; bg[h*2][1]=r1; bg[h*2+1][0]=r2; bg[h*2+1][1]=r3;
                LDSM4T(r0,r1,r2,r3, ubase + off);
                bu[h*2][0]=r0; bu[h*2][1]=r1; bu[h*2+1][0]=r2; bu[h*2+1][1]=r3;
            }
            #pragma unroll
            for (int mt = 0; mt < 4; mt++)
                #pragma unroll
                for (int nt = 0; nt < 4; nt++) {
                    MMA16816(ag[mt][nt], a[mt], bg[nt]);
                    MMA16816(au[mt][nt], a[mt], bu[nt]);
                }
        }
        if (kc + 2 < KC) issue(kc + 2);
    }

    // epilogue: bias + clip + glu in registers -> half2 stores
    const float* b1e = b1 + (size_t)e * (2*IDIM);
    int r0 = lane >> 2, cc = (lane & 3) * 2;
    #pragma unroll
    for (int nt = 0; nt < 4; nt++) {
        int col = n0 + wn*32 + nt*8 + cc;
        float G0 = b1e[col], G1 = b1e[col+1];
        float U0 = b1e[IDIM + col], U1 = b1e[IDIM + col + 1];
        #pragma unroll
        for (int mt = 0; mt < 4; mt++) {
            int grow = row0 + wm*64 + mt*16;
            float a0 = actf(ag[mt][nt][0] + G0, au[mt][nt][0] + U0);
            float a1 = actf(ag[mt][nt][1] + G1, au[mt][nt][1] + U1);
            float a2 = actf(ag[mt][nt][2] + G0, au[mt][nt][2] + U0);
            float a3 = actf(ag[mt][nt][3] + G1, au[mt][nt][3] + U1);
            __half2 h01 = __floats2half2_rn(a0, a1);
            __half2 h23 = __floats2half2_rn(a2, a3);
            *(__half2*)&g_acth[(size_t)(grow + r0) * IDIM + col]     = h01;
            *(__half2*)&g_acth[(size_t)(grow + r0 + 8) * IDIM + col] = h23;
        }
    }
}

// ---------------- GEMM2 (mma.sync fp16): out += w * (acth @ w2 + b2) ---------
__global__ void __launch_bounds__(256, 1) gemm2_kernel(const float* __restrict__ b2,
                                                       float* __restrict__ out)
{
    int by = blockIdx.y;
    int e = g_tile_expert[by];
    if (e < 0) return;
    int n0 = blockIdx.x * BN;
    int row0 = by * BM;
    int tid = threadIdx.x, lane = tid & 31, wid = tid >> 5;
    int wm = wid & 1, wn = wid >> 1;

    extern __shared__ char smem[];
    uint32_t sb = smem_u32(smem);
    __shared__ int   s_tok[BM];
    __shared__ float s_wt[BM];
    if (tid < BM) {
        s_tok[tid] = g_pair_tok[row0 + tid];
        s_wt[tid]  = g_pair_w[row0 + tid];
    }
    __syncthreads();

    const __half* w2e = g_w2h + (size_t)e * IDIM * HDIM;

    auto issue = [&](int kc) {
        int slot = kc % NSTAGE;
        uint32_t abase = sb + slot * ST_A;
        uint32_t bbase = sb + OFF_B2 + slot * ST_A;
        int k0 = kc * BK;
        #pragma unroll
        for (int i = 0; i < 4; i++) {
            int id = tid + i * 256;
            int r = id >> 3, c = id & 7;
            const __half* src = g_acth + (size_t)(row0 + r) * IDIM + k0 + c*8;
            CP16(abase + swzA((uint32_t)(r*128 + c*16)), src);
        }
        #pragma unroll
        for (int i = 0; i < 4; i++) {
            int id = tid + i * 256;
            int r = id >> 4, c = id & 15;
            const __half* src = w2e + (size_t)(k0 + r) * HDIM + n0 + c*8;
            CP16(bbase + swzB((uint32_t)(r*256 + c*16)), src);
        }
        CP_COMMIT();
    };

    float acc[4][4][4] = {};
    issue(0); issue(1);

    for (int kc = 0; kc < KC; kc++) {
        int slot = kc % NSTAGE;
        if (kc >= KC - 2) { CP_WAIT0(); } else { CP_WAIT1(); }
        __syncthreads();
        uint32_t abase = sb + slot * ST_A;
        uint32_t bbase = sb + OFF_B2 + slot * ST_A;
        #pragma unroll
        for (int k16 = 0; k16 < 4; k16++) {
            uint32_t a[4][4];
            #pragma unroll
            for (int mt = 0; mt < 4; mt++) {
                int mrow = wm*64 + mt*16 + (lane & 15);
                uint32_t addr = abase + swzA((uint32_t)(mrow*128 + (k16*2 + (lane>>4))*16));
                LDSM4(a[mt][0], a[mt][1], a[mt][2], a[mt][3], addr);
            }
            uint32_t b[4][2];
            #pragma unroll
            for (int h = 0; h < 2; h++) {
                int krow = k16*16 + (lane & 15);
                int nh = wn*32 + h*16 + (lane>>4)*8;
                uint32_t off = swzB((uint32_t)(krow*256 + nh*2));
                uint32_t r0,r1,r2,r3;
                LDSM4T(r0,r1,r2,r3, bbase + off);
                b[h*2][0]=r0; b[h*2][1]=r1; b[h*2+1][0]=r2; b[h*2+1][1]=r3;
            }
            #pragma unroll
            for (int mt = 0; mt < 4; mt++)
                #pragma unroll
                for (int nt = 0; nt < 4; nt++)
                    MMA16816(acc[mt][nt], a[mt], b[nt]);
        }
        if (kc + 2 < KC) issue(kc + 2);
    }

    // epilogue: +bias, *routing weight, atomic scatter by token
    const float* b2e = b2 + (size_t)e * HDIM;
    int r0 = lane >> 2, cc = (lane & 3) * 2;
    #pragma unroll
    for (int mt = 0; mt < 4; mt++) {
        int mrow = wm*64 + mt*16;
        int rA = mrow + r0, rB = rA + 8;
        int tokA = s_tok[rA], tokB = s_tok[rB];
        float wA = s_wt[rA], wB = s_wt[rB];
        #pragma unroll
        for (int nt = 0; nt < 4; nt++) {
            int col = n0 + wn*32 + nt*8 + cc;
            float B0 = b2e[col], B1 = b2e[col+1];
            if (tokA >= 0) {
                atomicAdd(&out[(size_t)tokA * HDIM + col],     (acc[mt][nt][0] + B0) * wA);
                atomicAdd(&out[(size_t)tokA * HDIM + col + 1], (acc[mt][nt][1] + B1) * wA);
            }
            if (tokB >= 0) {
                atomicAdd(&out[(size_t)tokB * HDIM + col],     (acc[mt][nt][2] + B0) * wB);
                atomicAdd(&out[(size_t)tokB * HDIM + col + 1], (acc[mt][nt][3] + B1) * wB);
            }
        }
    }
}

// ---------------- launch ------------------------------------------------------
extern "C" void kernel_launch(void* const* d_in, const int* in_sizes, int n_in,
                              void* d_out, int out_size)
{
    const float* x  = (const float*)d_in[0];
    const float* rw = (const float*)d_in[1];
    const float* rb = (const float*)d_in[2];
    const float* w1 = (const float*)d_in[3];
    const float* b1 = (const float*)d_in[4];
    const float* w2 = (const float*)d_in[5];
    const float* b2 = (const float*)d_in[6];
    float* out = (float*)d_out;

    int T = in_sizes[0] / HDIM;
    if (T > T_MAX) T = T_MAX;

    cudaFuncSetAttribute(gemm1_kernel, cudaFuncAttributeMaxDynamicSharedMemorySize, SMEM1);
    cudaFuncSetAttribute(gemm2_kernel, cudaFuncAttributeMaxDynamicSharedMemorySize, SMEM2);

    __half *w1h_p, *w2h_p, *xh_p;
    cudaGetSymbolAddress((void**)&w1h_p, g_w1h);
    cudaGetSymbolAddress((void**)&w2h_p, g_w2h);
    cudaGetSymbolAddress((void**)&xh_p, g_xh);

    cudaMemsetAsync(out, 0, (size_t)T * HDIM * sizeof(float));

    cvt_kernel<<<2048, 256>>>((const float4*)w1, (uint2*)w1h_p, NEXP*HDIM*2*IDIM/4);
    cvt_kernel<<<2048, 256>>>((const float4*)w2, (uint2*)w2h_p, NEXP*IDIM*HDIM/4);
    cvt_kernel<<<512, 256>>>((const float4*)x, (uint2*)xh_p, T*HDIM/4);

    router_kernel<<<T, 128>>>(x, rw, rb, T);
    count_kernel<<<NEXP, 256>>>(T);
    init_kernel<<<(MAX_ROWS + 255)/256, 256>>>();
    offsets_kernel<<<1, 1>>>();
    fill_kernel<<<NEXP, 256>>>(T);
    gemm1_kernel<<<dim3(IDIM/BN, MAX_TILES), 256, SMEM1>>>(b1);
    gemm2_kernel<<<dim3(HDIM/BN, MAX_TILES), 256, SMEM2>>>(b2, out);
}